// round 14
// baseline (speedup 1.0000x reference)
#include <cuda_runtime.h>
#include <cuda_bf16.h>
#include <cuda_fp16.h>
#include <cstdint>

#define NN 400000
#define EE 3200000
#define HH 100
#define NB_SCAN 391     // ceil(NN/1024)

typedef unsigned long long u64;

// ---------------- scratch (static device memory; no allocations) ------------
__device__ int   g_is64;
__device__ int   g_outdeg[NN];
__device__ int   g_indeg[NN];
__device__ int   g_rowptr[NN + 1];
__device__ int   g_blocksums[NB_SCAN];
__device__ int   g_blockoff[NB_SCAN];
__device__ int   g_cursor[NN];
__device__ float g_dinv[NN];
__device__ __align__(16) int2 g_csredge[EE];   // (src, w-bits)

__device__ float g_h [(size_t)NN * HH];
__device__ float g_t1[(size_t)NN * HH];
__device__ float g_t2[(size_t)NN * HH];
__device__ float g_t3[(size_t)NN * HH];
__device__ float g_t4[(size_t)NN * HH];
__device__ float g_z [(size_t)NN * HH];

// fp16 gather mirrors: 64 half2 per row (=128 halfs, 256B, line-aligned).
__device__ uint32_t g_hf [(size_t)NN * 64];
__device__ uint32_t g_t1f[(size_t)NN * 64];
__device__ uint32_t g_t2f[(size_t)NN * 64];
__device__ uint32_t g_t3f[(size_t)NN * 64];

__device__ float g_s1[NN * 2];
__device__ float g_s2[NN * 2];
__device__ float g_s3[NN * 2];
__device__ float g_s4[NN * 2];

__device__ float g_colsum[HH];
__device__ float g_colsq [HH];
__device__ __align__(16) float g_bna[HH];
__device__ __align__(16) float g_bnb[HH];

// pre-split fp16 weights, layout [n(128)][k(640)] — 10 chunks of 64 K each.
// hi = fp16(w), lo = fp16(w - hi): together ~22 significant bits (near exact).
#define WK 640
__device__ __align__(16) __half g_whi[128 * WK];
__device__ __align__(16) __half g_wlo[128 * WK];

// ---------------- edge dtype detection --------------------------------------
__global__ void k_detect(const void* __restrict__ ei) {
    const long long* p = (const long long*)ei;
    int is64 = 1;
    for (int i = 0; i < 256; i++) {
        long long v = p[i];
        if (v < 0 || v >= NN) { is64 = 0; break; }
    }
    g_is64 = is64;
}

__device__ __forceinline__ void load_edge(const void* __restrict__ ei, int e,
                                          int& s, int& d) {
    if (g_is64) {
        const long long* p = (const long long*)ei;
        s = (int)p[e];
        d = (int)p[EE + e];
    } else {
        const int* p = (const int*)ei;
        s = p[e];
        d = p[EE + e];
    }
}

// ---------------- preprocessing ---------------------------------------------
__global__ void k_zero_pre() {
    int i = blockIdx.x * blockDim.x + threadIdx.x;
    if (i < NN) { g_outdeg[i] = 0; g_indeg[i] = 0; g_cursor[i] = 0; }
    if (i < HH) { g_colsum[i] = 0.f; g_colsq[i] = 0.f; }
}

__global__ void k_hist(const void* __restrict__ ei) {
    int e = blockIdx.x * blockDim.x + threadIdx.x;
    if (e < EE) {
        int s, d;
        load_edge(ei, e, s, d);
        atomicAdd(&g_outdeg[s], 1);
        atomicAdd(&g_indeg[d], 1);
    }
}

__global__ void k_dinv() {
    int i = blockIdx.x * blockDim.x + threadIdx.x;
    if (i < NN) {
        int d = g_outdeg[i];
        g_dinv[i] = (d > 0) ? rsqrtf((float)d) : 0.0f;
    }
}

__global__ void k_scan1() {
    __shared__ int sm[1024];
    int t = threadIdx.x;
    int i = blockIdx.x * 1024 + t;
    int v = (i < NN) ? g_indeg[i] : 0;
    sm[t] = v;
    __syncthreads();
    for (int off = 1; off < 1024; off <<= 1) {
        int x = (t >= off) ? sm[t - off] : 0;
        __syncthreads();
        sm[t] += x;
        __syncthreads();
    }
    if (i < NN) g_rowptr[i] = sm[t] - v;
    if (t == 1023) g_blocksums[blockIdx.x] = sm[t];
}

__global__ void k_scan2() {
    __shared__ int sm[512];
    int t = threadIdx.x;
    int v = (t < NB_SCAN) ? g_blocksums[t] : 0;
    sm[t] = v;
    __syncthreads();
    for (int off = 1; off < 512; off <<= 1) {
        int x = (t >= off) ? sm[t - off] : 0;
        __syncthreads();
        sm[t] += x;
        __syncthreads();
    }
    if (t < NB_SCAN) g_blockoff[t] = sm[t] - v;
}

__global__ void k_scan3() {
    int i = blockIdx.x * blockDim.x + threadIdx.x;
    if (i < NN) g_rowptr[i] += g_blockoff[i >> 10];
    if (i == 0) g_rowptr[NN] = EE;
}

__global__ void k_scatter(const void* __restrict__ ei) {
    int e = blockIdx.x * blockDim.x + threadIdx.x;
    if (e < EE) {
        int s, d;
        load_edge(ei, e, s, d);
        int pos = g_rowptr[d] + atomicAdd(&g_cursor[d], 1);
        float w = -g_dinv[s] * g_dinv[d];
        g_csredge[pos] = make_int2(s, __float_as_int(w));
    }
}

// ---------------- layer-0 propagation (width 2) ------------------------------
__global__ void k_prop2(const float* __restrict__ in, const float* __restrict__ sub,
                        float* __restrict__ out, float alpha, float beta) {
    int i = blockIdx.x * blockDim.x + threadIdx.x;
    if (i >= NN) return;
    int p0 = g_rowptr[i], p1 = g_rowptr[i + 1];
    float a0 = 0.f, a1 = 0.f;
    for (int p = p0; p < p1; p++) {
        int2 e = g_csredge[p];
        float w = __int_as_float(e.y);
        float2 v = *(const float2*)(in + 2 * (size_t)e.x);
        a0 += w * v.x;
        a1 += w * v.y;
    }
    float2 o;
    if (beta != 0.f) {
        float2 sv = *(const float2*)(sub + 2 * (size_t)i);
        o.x = alpha * a0 + beta * sv.x;
        o.y = alpha * a1 + beta * sv.y;
    } else {
        o.x = alpha * a0;
        o.y = alpha * a1;
    }
    *(float2*)(out + 2 * (size_t)i) = o;
}

// ---------------- layer-0 GEMM: [N,2]x5 -> [N,100], +bias, relu --------------
__global__ void k_gemm0(const float* __restrict__ x,  const float* __restrict__ s1,
                        const float* __restrict__ s2, const float* __restrict__ s3,
                        const float* __restrict__ s4, const float* __restrict__ W0,
                        const float* __restrict__ b0, float* __restrict__ Z) {
    __shared__ float sw[1000];
    __shared__ float sb[HH];
    int tid = threadIdx.y * 32 + threadIdx.x;
    for (int i = tid; i < 1000; i += 256) sw[i] = W0[i];
    for (int i = tid; i < HH; i += 256) sb[i] = b0[i];
    __syncthreads();

    int n = blockIdx.x * 8 + threadIdx.y;
    float v[10];
    v[0] = x[2 * n]; v[1] = x[2 * n + 1];
    v[2] = s1[2 * n]; v[3] = s1[2 * n + 1];
    v[4] = s2[2 * n]; v[5] = s2[2 * n + 1];
    v[6] = s3[2 * n]; v[7] = s3[2 * n + 1];
    v[8] = s4[2 * n]; v[9] = s4[2 * n + 1];

    #pragma unroll
    for (int j = 0; j < 4; j++) {
        int c = threadIdx.x + 32 * j;
        if (c < HH) {
            float acc = sb[c];
            #pragma unroll
            for (int k = 0; k < 5; k++) {
                acc += v[2 * k]     * sw[(2 * k) * HH + c];
                acc += v[2 * k + 1] * sw[(2 * k + 1) * HH + c];
            }
            Z[(size_t)n * HH + c] = fmaxf(acc, 0.0f);
        }
    }
}

// ---------------- width-100 propagation: warp per dst row --------------------
// Gather from fp16 mirror (256B-aligned rows -> exactly 2 lines per edge).
__global__ void __launch_bounds__(256) k_prop100(
    const uint32_t* __restrict__ inf, const float* __restrict__ sub,
    float* __restrict__ out, uint32_t* __restrict__ outf,
    float alpha, float beta) {
    int warp = (blockIdx.x * blockDim.x + threadIdx.x) >> 5;
    int lane = threadIdx.x & 31;
    if (warp >= NN) return;
    int p0 = g_rowptr[warp], p1 = g_rowptr[warp + 1];
    float a0 = 0.f, a1 = 0.f, a2 = 0.f, a3 = 0.f;
    #pragma unroll 2
    for (int p = p0; p < p1; p++) {
        int2 e = g_csredge[p];
        float w = __int_as_float(e.y);
        const uint32_t* r = inf + (size_t)e.x * 64;
        uint32_t u0 = r[lane];
        uint32_t u1 = r[32 + lane];        // lanes>=18 read zero padding
        float2 v0 = __half22float2(*reinterpret_cast<__half2*>(&u0));
        float2 v1 = __half22float2(*reinterpret_cast<__half2*>(&u1));
        a0 += w * v0.x;
        a1 += w * v0.y;
        a2 += w * v1.x;
        a3 += w * v1.y;
    }
    int c01 = 2 * lane;            // cols c01, c01+1
    int c23 = 64 + 2 * lane;       // cols c23, c23+1 (valid if lane < 18)
    float2 o01, o23;
    o01.x = alpha * a0; o01.y = alpha * a1;
    o23.x = alpha * a2; o23.y = alpha * a3;
    if (beta != 0.f) {
        const float* sb = sub + (size_t)warp * HH;
        float2 s01 = *(const float2*)(sb + c01);
        o01.x += beta * s01.x; o01.y += beta * s01.y;
        if (lane < 18) {
            float2 s23 = *(const float2*)(sb + c23);
            o23.x += beta * s23.x; o23.y += beta * s23.y;
        }
    }
    float* o = out + (size_t)warp * HH;
    *(float2*)(o + c01) = o01;
    if (lane < 18) *(float2*)(o + c23) = o23;
    if (outf) {
        uint32_t* of = outf + (size_t)warp * 64;
        __half2 h01 = __float22half2_rn(o01);
        of[lane] = *reinterpret_cast<uint32_t*>(&h01);
        __half2 h23 = (lane < 18) ? __float22half2_rn(o23)
                                  : __floats2half2_rn(0.f, 0.f);
        of[32 + lane] = *reinterpret_cast<uint32_t*>(&h23);
    }
}

// ---------------- weight pre-split (fp32 -> fp16 hi/lo, [n][k(640)]) ---------
__global__ void k_wsplit(const float* __restrict__ W) {
    int idx = blockIdx.x * 256 + threadIdx.x;
    if (idx >= 128 * WK) return;
    int n = idx / WK;
    int k = idx % WK;
    int ch = k >> 6, kk = k & 63;
    int buf = ch >> 1, col0 = (ch & 1) * 64;
    int nvalid = HH - col0;
    float w = 0.f;
    if (n < HH && kk < nvalid)
        w = W[(size_t)(buf * HH + col0 + kk) * HH + n];
    __half h = __float2half_rn(w);
    g_whi[idx] = h;
    g_wlo[idx] = __float2half_rn(w - __half2float(h));
}

// ---------------- HMMA GEMM (fp16): Z = relu([T0..T4]@Wcat + b) + BN stats ---
// D = A * Whi + A * Wlo  (2 MMA terms).  A = single fp16 rounding of fp32 T
// (error profile empirically ~= R11's 8.3e-4).  W split is near-exact.
// SK=36: fragment-load bank index (4g+tg) covers all 32 banks, conflict-free.
#define SK 36                       // 32-bit words per row (72 fp16)
#define SM_WORDS (128 * SK)         // 4608 words per array
#define SMEM_MMA_BYTES (3 * SM_WORDS * 4)   // 55296

__device__ __forceinline__ void mma_f16(float* c, const uint32_t* a,
                                        const uint32_t* b) {
    asm volatile(
        "mma.sync.aligned.m16n8k16.row.col.f32.f16.f16.f32 "
        "{%0,%1,%2,%3}, {%4,%5,%6,%7}, {%8,%9}, {%0,%1,%2,%3};"
        : "+f"(c[0]), "+f"(c[1]), "+f"(c[2]), "+f"(c[3])
        : "r"(a[0]), "r"(a[1]), "r"(a[2]), "r"(a[3]), "r"(b[0]), "r"(b[1]));
}

__global__ void __launch_bounds__(256) k_gemm_mma(
    const float* __restrict__ t0, const float* __restrict__ t1,
    const float* __restrict__ t2, const float* __restrict__ t3,
    const float* __restrict__ t4,
    const float* __restrict__ bias, float* __restrict__ Z) {
    extern __shared__ uint32_t smw[];
    uint32_t* sA   = smw;
    uint32_t* sBhi = smw + SM_WORDS;
    uint32_t* sBlo = smw + 2 * SM_WORDS;

    int tid = threadIdx.x;
    int wid = tid >> 5, lane = tid & 31;
    int g = lane >> 2, tg = lane & 3;
    int rowbase = blockIdx.x * 128;
    const float* bufs[5] = { t0, t1, t2, t3, t4 };
    int mbase0 = (wid & 1) * 64;        // M: 2 warps
    int nbase0 = (wid >> 1) * 32;       // N: 4 warps

    float acc[4][4][4];
    #pragma unroll
    for (int i = 0; i < 4; i++)
        #pragma unroll
        for (int j = 0; j < 4; j++)
            #pragma unroll
            for (int q = 0; q < 4; q++) acc[i][j][q] = 0.f;

    for (int ch = 0; ch < 10; ch++) {
        int buf = ch >> 1;
        int col0 = (ch & 1) * 64;
        int nvalid = HH - col0;          // 100 or 36
        __syncthreads();                 // prior chunk's compute done

        // ---- stage A: 128 rows x 64 k, fp32 -> single fp16 ----
        const float* A = bufs[buf];
        #pragma unroll
        for (int it = 0; it < 8; it++) {
            int slot = tid + it * 256;           // 0..2047
            int r  = slot >> 4;
            int c4 = (slot & 15) << 2;           // 0..60
            float4 v = make_float4(0.f, 0.f, 0.f, 0.f);
            if (c4 < nvalid)
                v = *(const float4*)(A + (size_t)(rowbase + r) * HH + col0 + c4);
            __half2 h01 = __floats2half2_rn(v.x, v.y);
            __half2 h23 = __floats2half2_rn(v.z, v.w);
            int w = r * SK + (c4 >> 1);
            sA[w]     = *(uint32_t*)&h01;
            sA[w + 1] = *(uint32_t*)&h23;
        }
        // ---- stage B: coalesced copy from pre-split global fp16 ----
        #pragma unroll
        for (int it = 0; it < 4; it++) {
            int slot = tid + it * 256;           // 0..1023
            int n  = slot >> 3;
            int k8 = (slot & 7) << 3;            // 8 fp16
            uint4 vh = *(const uint4*)(g_whi + n * WK + ch * 64 + k8);
            uint4 vl = *(const uint4*)(g_wlo + n * WK + ch * 64 + k8);
            int w = n * SK + (k8 >> 1);
            *(uint2*)&sBhi[w]     = make_uint2(vh.x, vh.y);
            *(uint2*)&sBhi[w + 2] = make_uint2(vh.z, vh.w);
            *(uint2*)&sBlo[w]     = make_uint2(vl.x, vl.y);
            *(uint2*)&sBlo[w + 2] = make_uint2(vl.z, vl.w);
        }
        __syncthreads();

        // ---- K16 steps: 4 for even chunks (100 valid k), 3 for odd (36) ----
        int nsteps = (ch & 1) ? 3 : 4;
        #pragma unroll 4
        for (int st = 0; st < nsteps; st++) {
            int kw = st * 8;
            uint32_t Ar[4][4];
            #pragma unroll
            for (int i = 0; i < 4; i++) {
                int r0 = (mbase0 + i * 16 + g) * SK + kw + tg;
                int r8 = r0 + 8 * SK;
                Ar[i][0] = sA[r0];     Ar[i][1] = sA[r8];
                Ar[i][2] = sA[r0 + 4]; Ar[i][3] = sA[r8 + 4];
            }
            uint32_t Bh[4][2], Bl[4][2];
            #pragma unroll
            for (int j = 0; j < 4; j++) {
                int n0 = (nbase0 + j * 8 + g) * SK + kw + tg;
                Bh[j][0] = sBhi[n0]; Bh[j][1] = sBhi[n0 + 4];
                Bl[j][0] = sBlo[n0]; Bl[j][1] = sBlo[n0 + 4];
            }
            #pragma unroll
            for (int i = 0; i < 4; i++)
                #pragma unroll
                for (int j = 0; j < 4; j++) {
                    mma_f16(acc[i][j], Ar[i], Bh[j]);
                    mma_f16(acc[i][j], Ar[i], Bl[j]);
                }
        }
    }

    // ---- epilogue: bias + relu + store + fused BN stats ----
    float* sstat = (float*)smw;          // reuse smem: [0..99]=sum [100..199]=sq
    __syncthreads();                     // mainloop smem reads done
    if (tid < 2 * HH) sstat[tid] = 0.f;
    __syncthreads();

    #pragma unroll
    for (int j = 0; j < 4; j++) {
        int col = nbase0 + j * 8 + tg * 2;
        bool valid = col < HH;
        float b0v = valid ? bias[col]     : 0.f;
        float b1v = valid ? bias[col + 1] : 0.f;
        float s0 = 0.f, q0 = 0.f, s1 = 0.f, q1 = 0.f;
        #pragma unroll
        for (int i = 0; i < 4; i++) {
            int row = rowbase + mbase0 + i * 16 + g;
            float v00 = fmaxf(acc[i][j][0] + b0v, 0.f);
            float v01 = fmaxf(acc[i][j][1] + b1v, 0.f);
            float v10 = fmaxf(acc[i][j][2] + b0v, 0.f);
            float v11 = fmaxf(acc[i][j][3] + b1v, 0.f);
            if (valid) {
                *(float2*)(Z + (size_t)row * HH + col)       = make_float2(v00, v01);
                *(float2*)(Z + (size_t)(row + 8) * HH + col) = make_float2(v10, v11);
            }
            s0 += v00 + v10; q0 += v00 * v00 + v10 * v10;
            s1 += v01 + v11; q1 += v01 * v01 + v11 * v11;
        }
        #pragma unroll
        for (int off = 4; off < 32; off <<= 1) {
            s0 += __shfl_xor_sync(0xFFFFFFFF, s0, off);
            q0 += __shfl_xor_sync(0xFFFFFFFF, q0, off);
            s1 += __shfl_xor_sync(0xFFFFFFFF, s1, off);
            q1 += __shfl_xor_sync(0xFFFFFFFF, q1, off);
        }
        if (valid && g == 0) {
            atomicAdd(&sstat[col],          s0);
            atomicAdd(&sstat[col + 1],      s1);
            atomicAdd(&sstat[HH + col],     q0);
            atomicAdd(&sstat[HH + col + 1], q1);
        }
    }
    __syncthreads();
    if (tid < HH) {
        atomicAdd(&g_colsum[tid], sstat[tid]);
        atomicAdd(&g_colsq[tid],  sstat[HH + tid]);
    }
}

// ---------------- batch-norm ------------------------------------------------
__global__ void k_stats(const float* __restrict__ Z) {
    int tx = threadIdx.x, ty = threadIdx.y;
    int r0 = blockIdx.x * 1000;
    float s[4] = {0, 0, 0, 0}, q[4] = {0, 0, 0, 0};
    for (int r = r0 + ty; r < r0 + 1000; r += 8) {
        const float* zr = Z + (size_t)r * HH;
        #pragma unroll
        for (int j = 0; j < 4; j++) {
            int c = tx + 32 * j;
            if (c < HH) {
                float v = zr[c];
                s[j] += v;
                q[j] += v * v;
            }
        }
    }
    #pragma unroll
    for (int j = 0; j < 4; j++) {
        int c = tx + 32 * j;
        if (c < HH) {
            atomicAdd(&g_colsum[c], s[j]);
            atomicAdd(&g_colsq[c], q[j]);
        }
    }
}

__global__ void k_bnfinal(const float* __restrict__ gamma, const float* __restrict__ beta) {
    int c = threadIdx.x;
    if (c < HH) {
        float m = g_colsum[c] * (1.0f / NN);
        float v = g_colsq[c] * (1.0f / NN) - m * m;
        float a = gamma[c] * rsqrtf(v + 1e-5f);
        g_bna[c] = a;
        g_bnb[c] = beta[c] - a * m;
        g_colsum[c] = 0.f;       // reset for next layer's stats
        g_colsq[c]  = 0.f;
    }
}

// normalize Z -> out (fp32, stride HH) + optional fp16 mirror (stride 64 u32)
__global__ void k_norm(const float* __restrict__ Z, float* __restrict__ out,
                       uint32_t* __restrict__ outf) {
    int i = blockIdx.x * blockDim.x + threadIdx.x;
    if (i >= NN * 25) return;
    int row = i / 25;
    int c0 = (i % 25) * 4;
    float4 z = *(const float4*)(Z + (size_t)row * HH + c0);
    float4 r;
    r.x = g_bna[c0]     * z.x + g_bnb[c0];
    r.y = g_bna[c0 + 1] * z.y + g_bnb[c0 + 1];
    r.z = g_bna[c0 + 2] * z.z + g_bnb[c0 + 2];
    r.w = g_bna[c0 + 3] * z.w + g_bnb[c0 + 3];
    *(float4*)(out + (size_t)row * HH + c0) = r;
    if (outf) {
        __half2 h01 = __floats2half2_rn(r.x, r.y);
        __half2 h23 = __floats2half2_rn(r.z, r.w);
        uint32_t* of = outf + (size_t)row * 64 + (c0 >> 1);
        of[0] = *reinterpret_cast<uint32_t*>(&h01);
        of[1] = *reinterpret_cast<uint32_t*>(&h23);
    }
}

// ---------------- host ------------------------------------------------------
extern "C" void kernel_launch(void* const* d_in, const int* in_sizes, int n_in,
                              void* d_out, int out_size) {
    const float* x     = (const float*)d_in[0];
    const void*  ei    = d_in[1];          // int32 or int64 — detected on device
    const float* W0    = (const float*)d_in[2];
    const float* b0    = (const float*)d_in[3];
    const float* Wr    = (const float*)d_in[4];
    const float* br    = (const float*)d_in[5];
    const float* gamma = (const float*)d_in[6];
    const float* beta  = (const float*)d_in[7];
    float* out = (float*)d_out;

    float *h, *t1, *t2, *t3, *t4, *z;
    uint32_t *hf, *t1f, *t2f, *t3f;
    float *s1, *s2, *s3, *s4;
    cudaGetSymbolAddress((void**)&h,  g_h);
    cudaGetSymbolAddress((void**)&t1, g_t1);
    cudaGetSymbolAddress((void**)&t2, g_t2);
    cudaGetSymbolAddress((void**)&t3, g_t3);
    cudaGetSymbolAddress((void**)&t4, g_t4);
    cudaGetSymbolAddress((void**)&z,  g_z);
    cudaGetSymbolAddress((void**)&hf,  g_hf);
    cudaGetSymbolAddress((void**)&t1f, g_t1f);
    cudaGetSymbolAddress((void**)&t2f, g_t2f);
    cudaGetSymbolAddress((void**)&t3f, g_t3f);
    cudaGetSymbolAddress((void**)&s1, g_s1);
    cudaGetSymbolAddress((void**)&s2, g_s2);
    cudaGetSymbolAddress((void**)&s3, g_s3);
    cudaGetSymbolAddress((void**)&s4, g_s4);

    cudaFuncSetAttribute(k_gemm_mma, cudaFuncAttributeMaxDynamicSharedMemorySize,
                         SMEM_MMA_BYTES);

    const int TB = 256;
    const int gN = (NN + TB - 1) / TB;   // 1563
    const int gE = (EE + TB - 1) / TB;   // 12500

    // ---- CSR preprocessing (dst-sorted, atomic-free props afterwards) ----
    k_detect<<<1, 1>>>(ei);
    k_zero_pre<<<gN, TB>>>();
    k_hist<<<gE, TB>>>(ei);
    k_dinv<<<gN, TB>>>();
    k_scan1<<<NB_SCAN, 1024>>>();
    k_scan2<<<1, 512>>>();
    k_scan3<<<gN, TB>>>();
    k_scatter<<<gE, TB>>>(ei);

    // ---- layer 0 (width F_IN=2) ----
    k_prop2<<<gN, TB>>>(x,  x,  s1, 1.f,  0.f);
    k_prop2<<<gN, TB>>>(s1, x,  s2, 2.f, -1.f);
    k_prop2<<<gN, TB>>>(s2, s1, s3, 2.f, -1.f);
    k_prop2<<<gN, TB>>>(s3, s2, s4, 2.f, -1.f);
    k_gemm0<<<NN / 8, dim3(32, 8)>>>(x, s1, s2, s3, s4, W0, b0, z);
    k_stats<<<400, dim3(32, 8)>>>(z);
    k_bnfinal<<<1, 128>>>(gamma, beta);
    k_norm<<<(NN * 25 + TB - 1) / TB, TB>>>(z, h, hf);

    // ---- layers 1..4 (width 100); BN stats fused into GEMM epilogue ----
    for (int l = 1; l < 5; l++) {
        k_prop100<<<NN / 8, TB>>>(hf,  h,  t1, t1f, 1.f,  0.f);
        k_prop100<<<NN / 8, TB>>>(t1f, h,  t2, t2f, 2.f, -1.f);
        k_prop100<<<NN / 8, TB>>>(t2f, t1, t3, t3f, 2.f, -1.f);
        k_prop100<<<NN / 8, TB>>>(t3f, t2, t4, (uint32_t*)nullptr, 2.f, -1.f);
        k_wsplit<<<320, 256>>>(Wr + (size_t)(l - 1) * 5 * HH * HH);
        k_gemm_mma<<<NN / 128, 256, SMEM_MMA_BYTES>>>(
            h, t1, t2, t3, t4, br + (l - 1) * HH, z);
        k_bnfinal<<<1, 128>>>(gamma + l * HH, beta + l * HH);
        if (l == 4)
            k_norm<<<(NN * 25 + TB - 1) / TB, TB>>>(z, out, (uint32_t*)nullptr);
        else
            k_norm<<<(NN * 25 + TB - 1) / TB, TB>>>(z, h, hf);
    }
}

// round 15
// speedup vs baseline: 1.2978x; 1.2978x over previous
#include <cuda_runtime.h>
#include <cuda_bf16.h>
#include <cuda_fp16.h>
#include <cstdint>

#define NN 400000
#define EE 3200000
#define HH 100
#define NB_SCAN 391     // ceil(NN/1024)

typedef unsigned long long u64;

// ---------------- scratch (static device memory; no allocations) ------------
__device__ int   g_is64;
__device__ int   g_outdeg[NN];
__device__ int   g_indeg[NN];
__device__ int   g_rowptr[NN + 1];
__device__ int   g_blocksums[NB_SCAN];
__device__ int   g_blockoff[NB_SCAN];
__device__ int   g_cursor[NN];
__device__ float g_dinv[NN];
__device__ __align__(16) int2 g_csredge[EE];   // (src, w-bits)

__device__ float g_h [(size_t)NN * HH];
__device__ float g_t1[(size_t)NN * HH];
__device__ float g_t2[(size_t)NN * HH];
__device__ float g_t3[(size_t)NN * HH];
__device__ float g_t4[(size_t)NN * HH];
__device__ float g_z [(size_t)NN * HH];

// fp16 gather mirrors: 64 half2 per row (=128 halfs, 256B, line-aligned).
__device__ uint32_t g_hf [(size_t)NN * 64];
__device__ uint32_t g_t1f[(size_t)NN * 64];
__device__ uint32_t g_t2f[(size_t)NN * 64];
__device__ uint32_t g_t3f[(size_t)NN * 64];

__device__ float g_s1[NN * 2];
__device__ float g_s2[NN * 2];
__device__ float g_s3[NN * 2];
__device__ float g_s4[NN * 2];

__device__ float g_colsum[HH];
__device__ float g_colsq [HH];
__device__ __align__(16) float g_bna[HH];
__device__ __align__(16) float g_bnb[HH];

// pre-split bf16 weights, layout [n(128)][k(640)] — 10 chunks of 64 K each
#define WK 640
__device__ __align__(16) __nv_bfloat16 g_whi[128 * WK];
__device__ __align__(16) __nv_bfloat16 g_wlo[128 * WK];

// ---------------- edge dtype detection --------------------------------------
__global__ void k_detect(const void* __restrict__ ei) {
    const long long* p = (const long long*)ei;
    int is64 = 1;
    for (int i = 0; i < 256; i++) {
        long long v = p[i];
        if (v < 0 || v >= NN) { is64 = 0; break; }
    }
    g_is64 = is64;
}

__device__ __forceinline__ void load_edge(const void* __restrict__ ei, int e,
                                          int& s, int& d) {
    if (g_is64) {
        const long long* p = (const long long*)ei;
        s = (int)p[e];
        d = (int)p[EE + e];
    } else {
        const int* p = (const int*)ei;
        s = p[e];
        d = p[EE + e];
    }
}

// ---------------- preprocessing ---------------------------------------------
__global__ void k_zero_pre() {
    int i = blockIdx.x * blockDim.x + threadIdx.x;
    if (i < NN) { g_outdeg[i] = 0; g_indeg[i] = 0; g_cursor[i] = 0; }
    if (i < HH) { g_colsum[i] = 0.f; g_colsq[i] = 0.f; }
}

__global__ void k_hist(const void* __restrict__ ei) {
    int e = blockIdx.x * blockDim.x + threadIdx.x;
    if (e < EE) {
        int s, d;
        load_edge(ei, e, s, d);
        atomicAdd(&g_outdeg[s], 1);
        atomicAdd(&g_indeg[d], 1);
    }
}

__global__ void k_dinv() {
    int i = blockIdx.x * blockDim.x + threadIdx.x;
    if (i < NN) {
        int d = g_outdeg[i];
        g_dinv[i] = (d > 0) ? rsqrtf((float)d) : 0.0f;
    }
}

__global__ void k_scan1() {
    __shared__ int sm[1024];
    int t = threadIdx.x;
    int i = blockIdx.x * 1024 + t;
    int v = (i < NN) ? g_indeg[i] : 0;
    sm[t] = v;
    __syncthreads();
    for (int off = 1; off < 1024; off <<= 1) {
        int x = (t >= off) ? sm[t - off] : 0;
        __syncthreads();
        sm[t] += x;
        __syncthreads();
    }
    if (i < NN) g_rowptr[i] = sm[t] - v;
    if (t == 1023) g_blocksums[blockIdx.x] = sm[t];
}

__global__ void k_scan2() {
    __shared__ int sm[512];
    int t = threadIdx.x;
    int v = (t < NB_SCAN) ? g_blocksums[t] : 0;
    sm[t] = v;
    __syncthreads();
    for (int off = 1; off < 512; off <<= 1) {
        int x = (t >= off) ? sm[t - off] : 0;
        __syncthreads();
        sm[t] += x;
        __syncthreads();
    }
    if (t < NB_SCAN) g_blockoff[t] = sm[t] - v;
}

__global__ void k_scan3() {
    int i = blockIdx.x * blockDim.x + threadIdx.x;
    if (i < NN) g_rowptr[i] += g_blockoff[i >> 10];
    if (i == 0) g_rowptr[NN] = EE;
}

__global__ void k_scatter(const void* __restrict__ ei) {
    int e = blockIdx.x * blockDim.x + threadIdx.x;
    if (e < EE) {
        int s, d;
        load_edge(ei, e, s, d);
        int pos = g_rowptr[d] + atomicAdd(&g_cursor[d], 1);
        float w = -g_dinv[s] * g_dinv[d];
        g_csredge[pos] = make_int2(s, __float_as_int(w));
    }
}

// ---------------- layer-0 propagation (width 2) ------------------------------
__global__ void k_prop2(const float* __restrict__ in, const float* __restrict__ sub,
                        float* __restrict__ out, float alpha, float beta) {
    int i = blockIdx.x * blockDim.x + threadIdx.x;
    if (i >= NN) return;
    int p0 = g_rowptr[i], p1 = g_rowptr[i + 1];
    float a0 = 0.f, a1 = 0.f;
    for (int p = p0; p < p1; p++) {
        int2 e = g_csredge[p];
        float w = __int_as_float(e.y);
        float2 v = *(const float2*)(in + 2 * (size_t)e.x);
        a0 += w * v.x;
        a1 += w * v.y;
    }
    float2 o;
    if (beta != 0.f) {
        float2 sv = *(const float2*)(sub + 2 * (size_t)i);
        o.x = alpha * a0 + beta * sv.x;
        o.y = alpha * a1 + beta * sv.y;
    } else {
        o.x = alpha * a0;
        o.y = alpha * a1;
    }
    *(float2*)(out + 2 * (size_t)i) = o;
}

// ---------------- layer-0 GEMM: [N,2]x5 -> [N,100], +bias, relu --------------
__global__ void k_gemm0(const float* __restrict__ x,  const float* __restrict__ s1,
                        const float* __restrict__ s2, const float* __restrict__ s3,
                        const float* __restrict__ s4, const float* __restrict__ W0,
                        const float* __restrict__ b0, float* __restrict__ Z) {
    __shared__ float sw[1000];
    __shared__ float sb[HH];
    int tid = threadIdx.y * 32 + threadIdx.x;
    for (int i = tid; i < 1000; i += 256) sw[i] = W0[i];
    for (int i = tid; i < HH; i += 256) sb[i] = b0[i];
    __syncthreads();

    int n = blockIdx.x * 8 + threadIdx.y;
    float v[10];
    v[0] = x[2 * n]; v[1] = x[2 * n + 1];
    v[2] = s1[2 * n]; v[3] = s1[2 * n + 1];
    v[4] = s2[2 * n]; v[5] = s2[2 * n + 1];
    v[6] = s3[2 * n]; v[7] = s3[2 * n + 1];
    v[8] = s4[2 * n]; v[9] = s4[2 * n + 1];

    #pragma unroll
    for (int j = 0; j < 4; j++) {
        int c = threadIdx.x + 32 * j;
        if (c < HH) {
            float acc = sb[c];
            #pragma unroll
            for (int k = 0; k < 5; k++) {
                acc += v[2 * k]     * sw[(2 * k) * HH + c];
                acc += v[2 * k + 1] * sw[(2 * k + 1) * HH + c];
            }
            Z[(size_t)n * HH + c] = fmaxf(acc, 0.0f);
        }
    }
}

// ---------------- width-100 propagation: warp per dst row --------------------
// Gather from fp16 mirror (256B-aligned rows -> exactly 2 lines per edge).
// unroll 4: MLP 8 outstanding lines per warp to hide L2 latency.
__global__ void __launch_bounds__(256) k_prop100(
    const uint32_t* __restrict__ inf, const float* __restrict__ sub,
    float* __restrict__ out, uint32_t* __restrict__ outf,
    float alpha, float beta) {
    int warp = (blockIdx.x * blockDim.x + threadIdx.x) >> 5;
    int lane = threadIdx.x & 31;
    if (warp >= NN) return;
    int p0 = g_rowptr[warp], p1 = g_rowptr[warp + 1];
    float a0 = 0.f, a1 = 0.f, a2 = 0.f, a3 = 0.f;
    #pragma unroll 4
    for (int p = p0; p < p1; p++) {
        int2 e = g_csredge[p];
        float w = __int_as_float(e.y);
        const uint32_t* r = inf + (size_t)e.x * 64;
        uint32_t u0 = r[lane];
        uint32_t u1 = r[32 + lane];        // lanes>=18 read zero padding
        float2 v0 = __half22float2(*reinterpret_cast<__half2*>(&u0));
        float2 v1 = __half22float2(*reinterpret_cast<__half2*>(&u1));
        a0 += w * v0.x;
        a1 += w * v0.y;
        a2 += w * v1.x;
        a3 += w * v1.y;
    }
    int c01 = 2 * lane;            // cols c01, c01+1
    int c23 = 64 + 2 * lane;       // cols c23, c23+1 (valid if lane < 18)
    float2 o01, o23;
    o01.x = alpha * a0; o01.y = alpha * a1;
    o23.x = alpha * a2; o23.y = alpha * a3;
    if (beta != 0.f) {
        const float* sb = sub + (size_t)warp * HH;
        float2 s01 = *(const float2*)(sb + c01);
        o01.x += beta * s01.x; o01.y += beta * s01.y;
        if (lane < 18) {
            float2 s23 = *(const float2*)(sb + c23);
            o23.x += beta * s23.x; o23.y += beta * s23.y;
        }
    }
    float* o = out + (size_t)warp * HH;
    *(float2*)(o + c01) = o01;
    if (lane < 18) *(float2*)(o + c23) = o23;
    if (outf) {
        uint32_t* of = outf + (size_t)warp * 64;
        __half2 h01 = __float22half2_rn(o01);
        of[lane] = *reinterpret_cast<uint32_t*>(&h01);
        __half2 h23 = (lane < 18) ? __float22half2_rn(o23)
                                  : __floats2half2_rn(0.f, 0.f);
        of[32 + lane] = *reinterpret_cast<uint32_t*>(&h23);
    }
}

// ---------------- weight pre-split (fp32 -> bf16 hi/lo, [n][k(640)]) ---------
__global__ void k_wsplit(const float* __restrict__ W) {
    int idx = blockIdx.x * 256 + threadIdx.x;
    if (idx >= 128 * WK) return;
    int n = idx / WK;
    int k = idx % WK;
    int ch = k >> 6, kk = k & 63;
    int buf = ch >> 1, col0 = (ch & 1) * 64;
    int nvalid = HH - col0;
    float w = 0.f;
    if (n < HH && kk < nvalid)
        w = W[(size_t)(buf * HH + col0 + kk) * HH + n];
    __nv_bfloat16 h = __float2bfloat16(w);
    g_whi[idx] = h;
    g_wlo[idx] = __float2bfloat16(w - __bfloat162float(h));
}

// ---------------- HMMA GEMM: Z = relu([T0..T4]@Wcat + b) + fused BN stats ----
// SK=36: fragment-load bank index (4g+tg) covers all 32 banks, conflict-free.
// N-warp trim: warp group at nbase0=96 computes only j=0 (cols 96-103); cols
// 104..127 were always discarded, so this is bit-identical and -19% MMAs.
#define SK 36                       // 32-bit words per row (72 bf16)
#define SM_WORDS (128 * SK)         // 4608 words per array
#define SMEM_MMA_BYTES (4 * SM_WORDS * 4)   // 73728

__device__ __forceinline__ void mma_bf16(float* c, const uint32_t* a,
                                         const uint32_t* b) {
    asm volatile(
        "mma.sync.aligned.m16n8k16.row.col.f32.bf16.bf16.f32 "
        "{%0,%1,%2,%3}, {%4,%5,%6,%7}, {%8,%9}, {%0,%1,%2,%3};"
        : "+f"(c[0]), "+f"(c[1]), "+f"(c[2]), "+f"(c[3])
        : "r"(a[0]), "r"(a[1]), "r"(a[2]), "r"(a[3]), "r"(b[0]), "r"(b[1]));
}

__global__ void __launch_bounds__(256) k_gemm_mma(
    const float* __restrict__ t0, const float* __restrict__ t1,
    const float* __restrict__ t2, const float* __restrict__ t3,
    const float* __restrict__ t4,
    const float* __restrict__ bias, float* __restrict__ Z) {
    extern __shared__ uint32_t smw[];
    uint32_t* sAhi = smw;
    uint32_t* sAlo = smw + SM_WORDS;
    uint32_t* sBhi = smw + 2 * SM_WORDS;
    uint32_t* sBlo = smw + 3 * SM_WORDS;

    int tid = threadIdx.x;
    int wid = tid >> 5, lane = tid & 31;
    int g = lane >> 2, tg = lane & 3;
    int rowbase = blockIdx.x * 128;
    const float* bufs[5] = { t0, t1, t2, t3, t4 };
    int mbase0 = (wid & 1) * 64;        // M: 2 warps
    int nbase0 = (wid >> 1) * 32;       // N: 4 warps
    const int jmax = (nbase0 == 96) ? 1 : 4;   // cols >= 104 are never stored

    float acc[4][4][4];
    #pragma unroll
    for (int i = 0; i < 4; i++)
        #pragma unroll
        for (int j = 0; j < 4; j++)
            #pragma unroll
            for (int q = 0; q < 4; q++) acc[i][j][q] = 0.f;

    for (int ch = 0; ch < 10; ch++) {
        int buf = ch >> 1;
        int col0 = (ch & 1) * 64;
        int nvalid = HH - col0;          // 100 or 36
        __syncthreads();                 // prior chunk's compute done

        // ---- stage A: 128 rows x 64 k, fp32 -> split bf16 ----
        const float* A = bufs[buf];
        #pragma unroll
        for (int it = 0; it < 8; it++) {
            int slot = tid + it * 256;           // 0..2047
            int r  = slot >> 4;
            int c4 = (slot & 15) << 2;           // 0..60
            float4 v = make_float4(0.f, 0.f, 0.f, 0.f);
            if (c4 < nvalid)
                v = *(const float4*)(A + (size_t)(rowbase + r) * HH + col0 + c4);
            __nv_bfloat162 h01 = __floats2bfloat162_rn(v.x, v.y);
            __nv_bfloat162 h23 = __floats2bfloat162_rn(v.z, v.w);
            __nv_bfloat162 l01 = __floats2bfloat162_rn(
                v.x - __bfloat162float(h01.x), v.y - __bfloat162float(h01.y));
            __nv_bfloat162 l23 = __floats2bfloat162_rn(
                v.z - __bfloat162float(h23.x), v.w - __bfloat162float(h23.y));
            int w = r * SK + (c4 >> 1);
            sAhi[w] = *(uint32_t*)&h01; sAhi[w + 1] = *(uint32_t*)&h23;
            sAlo[w] = *(uint32_t*)&l01; sAlo[w + 1] = *(uint32_t*)&l23;
        }
        // ---- stage B: coalesced copy from pre-split global bf16 ----
        #pragma unroll
        for (int it = 0; it < 4; it++) {
            int slot = tid + it * 256;           // 0..1023
            int n  = slot >> 3;
            int k8 = (slot & 7) << 3;            // 8 bf16
            uint4 vh = *(const uint4*)(g_whi + n * WK + ch * 64 + k8);
            uint4 vl = *(const uint4*)(g_wlo + n * WK + ch * 64 + k8);
            int w = n * SK + (k8 >> 1);
            *(uint2*)&sBhi[w]     = make_uint2(vh.x, vh.y);
            *(uint2*)&sBhi[w + 2] = make_uint2(vh.z, vh.w);
            *(uint2*)&sBlo[w]     = make_uint2(vl.x, vl.y);
            *(uint2*)&sBlo[w + 2] = make_uint2(vl.z, vl.w);
        }
        __syncthreads();

        // ---- K16 steps: 4 for even chunks (100 valid k), 3 for odd (36) ----
        int nsteps = (ch & 1) ? 3 : 4;
        #pragma unroll 4
        for (int st = 0; st < nsteps; st++) {
            int kw = st * 8;
            uint32_t Ah[4][4], Al[4][4];
            #pragma unroll
            for (int i = 0; i < 4; i++) {
                int r0 = (mbase0 + i * 16 + g) * SK + kw + tg;
                int r8 = r0 + 8 * SK;
                Ah[i][0] = sAhi[r0];     Ah[i][1] = sAhi[r8];
                Ah[i][2] = sAhi[r0 + 4]; Ah[i][3] = sAhi[r8 + 4];
                Al[i][0] = sAlo[r0];     Al[i][1] = sAlo[r8];
                Al[i][2] = sAlo[r0 + 4]; Al[i][3] = sAlo[r8 + 4];
            }
            uint32_t Bh[4][2], Bl[4][2];
            #pragma unroll
            for (int j = 0; j < 4; j++) {
                if (j < jmax) {
                    int n0 = (nbase0 + j * 8 + g) * SK + kw + tg;
                    Bh[j][0] = sBhi[n0]; Bh[j][1] = sBhi[n0 + 4];
                    Bl[j][0] = sBlo[n0]; Bl[j][1] = sBlo[n0 + 4];
                }
            }
            #pragma unroll
            for (int i = 0; i < 4; i++)
                #pragma unroll
                for (int j = 0; j < 4; j++) {
                    if (j < jmax) {
                        mma_bf16(acc[i][j], Ah[i], Bh[j]);
                        mma_bf16(acc[i][j], Al[i], Bh[j]);
                        mma_bf16(acc[i][j], Ah[i], Bl[j]);
                    }
                }
        }
    }

    // ---- epilogue: bias + relu + store + fused BN stats ----
    float* sstat = (float*)smw;          // reuse smem: [0..99]=sum [100..199]=sq
    __syncthreads();                     // mainloop smem reads done
    if (tid < 2 * HH) sstat[tid] = 0.f;
    __syncthreads();

    #pragma unroll
    for (int j = 0; j < 4; j++) {
        int col = nbase0 + j * 8 + tg * 2;
        bool valid = col < HH;
        float b0v = valid ? bias[col]     : 0.f;
        float b1v = valid ? bias[col + 1] : 0.f;
        float s0 = 0.f, q0 = 0.f, s1 = 0.f, q1 = 0.f;
        #pragma unroll
        for (int i = 0; i < 4; i++) {
            int row = rowbase + mbase0 + i * 16 + g;
            float v00 = fmaxf(acc[i][j][0] + b0v, 0.f);
            float v01 = fmaxf(acc[i][j][1] + b1v, 0.f);
            float v10 = fmaxf(acc[i][j][2] + b0v, 0.f);
            float v11 = fmaxf(acc[i][j][3] + b1v, 0.f);
            if (valid) {
                *(float2*)(Z + (size_t)row * HH + col)       = make_float2(v00, v01);
                *(float2*)(Z + (size_t)(row + 8) * HH + col) = make_float2(v10, v11);
            }
            s0 += v00 + v10; q0 += v00 * v00 + v10 * v10;
            s1 += v01 + v11; q1 += v01 * v01 + v11 * v11;
        }
        #pragma unroll
        for (int off = 4; off < 32; off <<= 1) {
            s0 += __shfl_xor_sync(0xFFFFFFFF, s0, off);
            q0 += __shfl_xor_sync(0xFFFFFFFF, q0, off);
            s1 += __shfl_xor_sync(0xFFFFFFFF, s1, off);
            q1 += __shfl_xor_sync(0xFFFFFFFF, q1, off);
        }
        if (valid && g == 0) {
            atomicAdd(&sstat[col],          s0);
            atomicAdd(&sstat[col + 1],      s1);
            atomicAdd(&sstat[HH + col],     q0);
            atomicAdd(&sstat[HH + col + 1], q1);
        }
    }
    __syncthreads();
    if (tid < HH) {
        atomicAdd(&g_colsum[tid], sstat[tid]);
        atomicAdd(&g_colsq[tid],  sstat[HH + tid]);
    }
}

// ---------------- batch-norm ------------------------------------------------
__global__ void k_stats(const float* __restrict__ Z) {
    int tx = threadIdx.x, ty = threadIdx.y;
    int r0 = blockIdx.x * 1000;
    float s[4] = {0, 0, 0, 0}, q[4] = {0, 0, 0, 0};
    for (int r = r0 + ty; r < r0 + 1000; r += 8) {
        const float* zr = Z + (size_t)r * HH;
        #pragma unroll
        for (int j = 0; j < 4; j++) {
            int c = tx + 32 * j;
            if (c < HH) {
                float v = zr[c];
                s[j] += v;
                q[j] += v * v;
            }
        }
    }
    #pragma unroll
    for (int j = 0; j < 4; j++) {
        int c = tx + 32 * j;
        if (c < HH) {
            atomicAdd(&g_colsum[c], s[j]);
            atomicAdd(&g_colsq[c], q[j]);
        }
    }
}

__global__ void k_bnfinal(const float* __restrict__ gamma, const float* __restrict__ beta) {
    int c = threadIdx.x;
    if (c < HH) {
        float m = g_colsum[c] * (1.0f / NN);
        float v = g_colsq[c] * (1.0f / NN) - m * m;
        float a = gamma[c] * rsqrtf(v + 1e-5f);
        g_bna[c] = a;
        g_bnb[c] = beta[c] - a * m;
        g_colsum[c] = 0.f;       // reset for next layer's stats
        g_colsq[c]  = 0.f;
    }
}

// normalize Z -> out (fp32, stride HH) + optional fp16 mirror (stride 64 u32)
__global__ void k_norm(const float* __restrict__ Z, float* __restrict__ out,
                       uint32_t* __restrict__ outf) {
    int i = blockIdx.x * blockDim.x + threadIdx.x;
    if (i >= NN * 25) return;
    int row = i / 25;
    int c0 = (i % 25) * 4;
    float4 z = *(const float4*)(Z + (size_t)row * HH + c0);
    float4 r;
    r.x = g_bna[c0]     * z.x + g_bnb[c0];
    r.y = g_bna[c0 + 1] * z.y + g_bnb[c0 + 1];
    r.z = g_bna[c0 + 2] * z.z + g_bnb[c0 + 2];
    r.w = g_bna[c0 + 3] * z.w + g_bnb[c0 + 3];
    *(float4*)(out + (size_t)row * HH + c0) = r;
    if (outf) {
        __half2 h01 = __floats2half2_rn(r.x, r.y);
        __half2 h23 = __floats2half2_rn(r.z, r.w);
        uint32_t* of = outf + (size_t)row * 64 + (c0 >> 1);
        of[0] = *reinterpret_cast<uint32_t*>(&h01);
        of[1] = *reinterpret_cast<uint32_t*>(&h23);
    }
}

// ---------------- host ------------------------------------------------------
extern "C" void kernel_launch(void* const* d_in, const int* in_sizes, int n_in,
                              void* d_out, int out_size) {
    const float* x     = (const float*)d_in[0];
    const void*  ei    = d_in[1];          // int32 or int64 — detected on device
    const float* W0    = (const float*)d_in[2];
    const float* b0    = (const float*)d_in[3];
    const float* Wr    = (const float*)d_in[4];
    const float* br    = (const float*)d_in[5];
    const float* gamma = (const float*)d_in[6];
    const float* beta  = (const float*)d_in[7];
    float* out = (float*)d_out;

    float *h, *t1, *t2, *t3, *t4, *z;
    uint32_t *hf, *t1f, *t2f, *t3f;
    float *s1, *s2, *s3, *s4;
    cudaGetSymbolAddress((void**)&h,  g_h);
    cudaGetSymbolAddress((void**)&t1, g_t1);
    cudaGetSymbolAddress((void**)&t2, g_t2);
    cudaGetSymbolAddress((void**)&t3, g_t3);
    cudaGetSymbolAddress((void**)&t4, g_t4);
    cudaGetSymbolAddress((void**)&z,  g_z);
    cudaGetSymbolAddress((void**)&hf,  g_hf);
    cudaGetSymbolAddress((void**)&t1f, g_t1f);
    cudaGetSymbolAddress((void**)&t2f, g_t2f);
    cudaGetSymbolAddress((void**)&t3f, g_t3f);
    cudaGetSymbolAddress((void**)&s1, g_s1);
    cudaGetSymbolAddress((void**)&s2, g_s2);
    cudaGetSymbolAddress((void**)&s3, g_s3);
    cudaGetSymbolAddress((void**)&s4, g_s4);

    cudaFuncSetAttribute(k_gemm_mma, cudaFuncAttributeMaxDynamicSharedMemorySize,
                         SMEM_MMA_BYTES);

    const int TB = 256;
    const int gN = (NN + TB - 1) / TB;   // 1563
    const int gE = (EE + TB - 1) / TB;   // 12500

    // ---- CSR preprocessing (dst-sorted, atomic-free props afterwards) ----
    k_detect<<<1, 1>>>(ei);
    k_zero_pre<<<gN, TB>>>();
    k_hist<<<gE, TB>>>(ei);
    k_dinv<<<gN, TB>>>();
    k_scan1<<<NB_SCAN, 1024>>>();
    k_scan2<<<1, 512>>>();
    k_scan3<<<gN, TB>>>();
    k_scatter<<<gE, TB>>>(ei);

    // ---- layer 0 (width F_IN=2) ----
    k_prop2<<<gN, TB>>>(x,  x,  s1, 1.f,  0.f);
    k_prop2<<<gN, TB>>>(s1, x,  s2, 2.f, -1.f);
    k_prop2<<<gN, TB>>>(s2, s1, s3, 2.f, -1.f);
    k_prop2<<<gN, TB>>>(s3, s2, s4, 2.f, -1.f);
    k_gemm0<<<NN / 8, dim3(32, 8)>>>(x, s1, s2, s3, s4, W0, b0, z);
    k_stats<<<400, dim3(32, 8)>>>(z);
    k_bnfinal<<<1, 128>>>(gamma, beta);
    k_norm<<<(NN * 25 + TB - 1) / TB, TB>>>(z, h, hf);

    // ---- layers 1..4 (width 100); BN stats fused into GEMM epilogue ----
    for (int l = 1; l < 5; l++) {
        k_prop100<<<NN / 8, TB>>>(hf,  h,  t1, t1f, 1.f,  0.f);
        k_prop100<<<NN / 8, TB>>>(t1f, h,  t2, t2f, 2.f, -1.f);
        k_prop100<<<NN / 8, TB>>>(t2f, t1, t3, t3f, 2.f, -1.f);
        k_prop100<<<NN / 8, TB>>>(t3f, t2, t4, (uint32_t*)nullptr, 2.f, -1.f);
        k_wsplit<<<320, 256>>>(Wr + (size_t)(l - 1) * 5 * HH * HH);
        k_gemm_mma<<<NN / 128, 256, SMEM_MMA_BYTES>>>(
            h, t1, t2, t3, t4, br + (l - 1) * HH, z);
        k_bnfinal<<<1, 128>>>(gamma + l * HH, beta + l * HH);
        if (l == 4)
            k_norm<<<(NN * 25 + TB - 1) / TB, TB>>>(z, out, (uint32_t*)nullptr);
        else
            k_norm<<<(NN * 25 + TB - 1) / TB, TB>>>(z, h, hf);
    }
}